// round 7
// baseline (speedup 1.0000x reference)
#include <cuda_runtime.h>

#define N_NODES 100000
#define N_EDGES 600000
#define F_IN 128
#define F_OUT 64
#define TM 128
#define BK 16
#define AS_PITCH 132

// Scratch (no allocation allowed in kernel_launch)
__device__ float s_xp[(size_t)N_NODES * F_OUT];
__device__ float s_deg[N_NODES];   // zero-initialized; k_dis re-zeroes after use
__device__ float s_dis[N_NODES];
__device__ float s_inv_sigma;

// ---------------------------------------------------------------------------
// sigma = ||W (W^T u / ||W^T u||)||  ->  store 1/sigma
// ---------------------------------------------------------------------------
__global__ void k_sigma(const float* __restrict__ W, const float* __restrict__ u) {
    __shared__ float v[F_OUT];
    __shared__ float red[128];
    __shared__ float n1_s;
    int t = threadIdx.x;

    if (t < F_OUT) {
        float s = 0.f;
        for (int i = 0; i < F_IN; i++) s += W[i * F_OUT + t] * u[i];
        v[t] = s;
    }
    __syncthreads();

    red[t] = (t < F_OUT) ? v[t] * v[t] : 0.f;
    __syncthreads();
    for (int s = 64; s > 0; s >>= 1) {
        if (t < s) red[t] += red[t + s];
        __syncthreads();
    }
    if (t == 0) n1_s = sqrtf(red[0]);
    __syncthreads();

    float g = 0.f;
    for (int j = 0; j < F_OUT; j++) g += W[t * F_OUT + j] * v[j];
    red[t] = g * g;
    __syncthreads();
    for (int s = 64; s > 0; s >>= 1) {
        if (t < s) red[t] += red[t + s];
        __syncthreads();
    }
    if (t == 0) {
        float n2 = sqrtf(red[0]);
        s_inv_sigma = n1_s / n2;   // 1/sigma = ||v_raw|| / ||W v_raw||
    }
}

// ---------------------------------------------------------------------------
// deg accumulation (deg starts at 0 each replay; self-loop +1 folded at use)
// ---------------------------------------------------------------------------
__global__ void k_deg_acc(const int* __restrict__ ei,
                          const float* __restrict__ ew) {
    int e = blockIdx.x * blockDim.x + threadIdx.x;
    if (e < N_EDGES) {
        int col = ei[N_EDGES + e];
        float w = 1.f / (1.f + __expf(-ew[e]));
        atomicAdd(&s_deg[col], w);
    }
}

// dis = rsqrt(deg + 1), then reset deg to 0 for the next graph replay.
// Runs AFTER k_gemm (gemm reads s_deg directly), before k_edge.
__global__ void k_dis() {
    int i = blockIdx.x * blockDim.x + threadIdx.x;
    if (i < N_NODES) {
        float d = s_deg[i] + 1.0f;
        s_dis[i] = rsqrtf(d);
        s_deg[i] = 0.0f;
    }
}

// ---------------------------------------------------------------------------
// xp = x @ (W/sigma); out = xp/(deg+1) + bias (self-loop); stash xp in L2.
// 128 rows x 64 cols per block, 128 threads, 8x8 per-thread scalar tile.
// ---------------------------------------------------------------------------
__global__ __launch_bounds__(128, 4) void k_gemm(const float* __restrict__ x,
                                                 const float* __restrict__ W,
                                                 const float* __restrict__ bias,
                                                 float* __restrict__ out) {
    __shared__ float Ws[F_IN][F_OUT];        // 32 KB (scaled by 1/sigma)
    __shared__ float As[BK][AS_PITCH];       // 8.4 KB, transposed A chunk

    int tid = threadIdx.x;
    int tx = tid & 7;       // col group: 8 cols each
    int ty = tid >> 3;      // row group: 8 rows each (0..15)
    int r0 = blockIdx.x * TM;

    float inv_sigma = s_inv_sigma;
    {
        const float4* W4 = (const float4*)W;
        float4* Ws4 = (float4*)&Ws[0][0];
        #pragma unroll
        for (int i = tid; i < F_IN * F_OUT / 4; i += 128) {
            float4 wv = W4[i];
            Ws4[i] = make_float4(wv.x * inv_sigma, wv.y * inv_sigma,
                                 wv.z * inv_sigma, wv.w * inv_sigma);
        }
    }

    float acc[8][8];
    #pragma unroll
    for (int i = 0; i < 8; i++)
        #pragma unroll
        for (int j = 0; j < 8; j++) acc[i][j] = 0.f;

    for (int kc = 0; kc < F_IN; kc += BK) {
        __syncthreads();
        #pragma unroll
        for (int l = 0; l < 4; l++) {
            int idx = tid + l * 128;        // 0..511 float4 slots
            int row = idx >> 2;             // 0..127
            int kq  = idx & 3;              // float4 within k-chunk
            int grow = r0 + row;
            float4 val = make_float4(0.f, 0.f, 0.f, 0.f);
            if (grow < N_NODES)
                val = *(const float4*)&x[(size_t)grow * F_IN + kc + kq * 4];
            As[kq * 4 + 0][row] = val.x;
            As[kq * 4 + 1][row] = val.y;
            As[kq * 4 + 2][row] = val.z;
            As[kq * 4 + 3][row] = val.w;
        }
        __syncthreads();

        #pragma unroll
        for (int k = 0; k < BK; k++) {
            float4 a0 = *(const float4*)&As[k][ty * 8];
            float4 a1 = *(const float4*)&As[k][ty * 8 + 4];
            float4 b0 = *(const float4*)&Ws[kc + k][tx * 8];
            float4 b1 = *(const float4*)&Ws[kc + k][tx * 8 + 4];
            float av[8] = {a0.x, a0.y, a0.z, a0.w, a1.x, a1.y, a1.z, a1.w};
            float bv[8] = {b0.x, b0.y, b0.z, b0.w, b1.x, b1.y, b1.z, b1.w};
            #pragma unroll
            for (int i = 0; i < 8; i++)
                #pragma unroll
                for (int j = 0; j < 8; j++)
                    acc[i][j] += av[i] * bv[j];
        }
    }

    float4 bb0 = *(const float4*)&bias[tx * 8];
    float4 bb1 = *(const float4*)&bias[tx * 8 + 4];
    float bv[8] = {bb0.x, bb0.y, bb0.z, bb0.w, bb1.x, bb1.y, bb1.z, bb1.w};

    #pragma unroll
    for (int i = 0; i < 8; i++) {
        int row = r0 + ty * 8 + i;
        if (row < N_NODES) {
            float inv_deg = 1.0f / (s_deg[row] + 1.0f);
            float4 xp0 = make_float4(acc[i][0], acc[i][1], acc[i][2], acc[i][3]);
            float4 xp1 = make_float4(acc[i][4], acc[i][5], acc[i][6], acc[i][7]);
            *(float4*)&s_xp[(size_t)row * F_OUT + tx * 8]     = xp0;
            *(float4*)&s_xp[(size_t)row * F_OUT + tx * 8 + 4] = xp1;
            float4 o0 = make_float4(xp0.x * inv_deg + bv[0], xp0.y * inv_deg + bv[1],
                                    xp0.z * inv_deg + bv[2], xp0.w * inv_deg + bv[3]);
            float4 o1 = make_float4(xp1.x * inv_deg + bv[4], xp1.y * inv_deg + bv[5],
                                    xp1.z * inv_deg + bv[6], xp1.w * inv_deg + bv[7]);
            *(float4*)&out[(size_t)row * F_OUT + tx * 8]     = o0;
            *(float4*)&out[(size_t)row * F_OUT + tx * 8 + 4] = o1;
        }
    }
}

// ---------------------------------------------------------------------------
// Edge aggregation: out[col] += dis[row]*sigmoid(ew)*dis[col] * xp[row]
// 4 edges per warp: 16 lanes/edge, 2 edges sequentially per lane group
// (independent gathers issued together for MLP=2), float4 RED scatter.
// ---------------------------------------------------------------------------
__global__ __launch_bounds__(256) void k_edge(const int* __restrict__ ei,
                                              const float* __restrict__ ew,
                                              float* __restrict__ out) {
    int gtid = blockIdx.x * blockDim.x + threadIdx.x;
    int lane = threadIdx.x & 31;
    int half = lane >> 4;       // edge subgroup within warp
    int sub  = lane & 15;       // float4 slot within edge
    int ebase = (gtid >> 5) * 4 + half * 2;   // warp covers 4 edges

    int   rowv[2], colv[2];
    float cf[2];
    #pragma unroll
    for (int j = 0; j < 2; j++) {
        int e = ebase + j;
        rowv[j] = ei[e];
        colv[j] = ei[N_EDGES + e];
        float w = 1.f / (1.f + __expf(-ew[e]));
        cf[j] = s_dis[rowv[j]] * w * s_dis[colv[j]];
    }

    float4 xv0 = *(const float4*)&s_xp[(size_t)rowv[0] * F_OUT + sub * 4];
    float4 xv1 = *(const float4*)&s_xp[(size_t)rowv[1] * F_OUT + sub * 4];

    float4 m0 = make_float4(xv0.x * cf[0], xv0.y * cf[0], xv0.z * cf[0], xv0.w * cf[0]);
    atomicAdd((float4*)&out[(size_t)colv[0] * F_OUT + sub * 4], m0);
    float4 m1 = make_float4(xv1.x * cf[1], xv1.y * cf[1], xv1.z * cf[1], xv1.w * cf[1]);
    atomicAdd((float4*)&out[(size_t)colv[1] * F_OUT + sub * 4], m1);
}

// ---------------------------------------------------------------------------
extern "C" void kernel_launch(void* const* d_in, const int* in_sizes, int n_in,
                              void* d_out, int out_size) {
    const float* x    = (const float*)d_in[0];
    const int*   ei   = (const int*)d_in[1];    // edge_index is int32 (JAX x64 off)
    const float* W    = (const float*)d_in[2];
    const float* bias = (const float*)d_in[3];
    const float* ew   = (const float*)d_in[4];
    const float* u    = (const float*)d_in[5];
    float* out = (float*)d_out;

    k_sigma<<<1, 128>>>(W, u);
    k_deg_acc<<<(N_EDGES + 255) / 256, 256>>>(ei, ew);
    k_gemm<<<(N_NODES + TM - 1) / TM, 128>>>(x, W, bias, out);  // reads s_deg
    k_dis<<<(N_NODES + 255) / 256, 256>>>();                    // makes s_dis, resets s_deg
    // 4 edges per warp: 600000/4 = 150000 warps / 8 per block = 18750 blocks
    k_edge<<<18750, 256>>>(ei, ew, out);
}

// round 10
// speedup vs baseline: 1.0968x; 1.0968x over previous
#include <cuda_runtime.h>
#include <cuda_bf16.h>
#include <cstdint>

#define N_NODES 100000
#define N_EDGES 600000
#define F_IN 128
#define F_OUT 64
#define TM 128
#define AP 136                 // smem pitch in bf16 (272B rows: 16B-aligned, conflict-free)

// Scratch (no allocation allowed in kernel_launch)
__device__ float s_xp[(size_t)N_NODES * F_OUT];
__device__ float s_deg[N_NODES];   // zero-init; k_dis re-zeroes after use
__device__ float s_dis[N_NODES];
__device__ float s_inv_sigma;

// dynamic smem byte offsets for k_gemm
#define SM_AHI 0                          // 128*136*2 = 34816
#define SM_ALO 34816
#define SM_BHI 69632                      // 64*136*2 = 17408
#define SM_BLO 87040
#define SM_TOTAL 104448

__device__ __forceinline__ uint32_t smem_u32(const void* p) {
    uint32_t a;
    asm("{ .reg .u64 t; cvta.to.shared.u64 t, %1; cvt.u32.u64 %0, t; }" : "=r"(a) : "l"(p));
    return a;
}

#define LDSM_X4(r, addr) \
    asm volatile("ldmatrix.sync.aligned.m8n8.x4.shared.b16 {%0,%1,%2,%3}, [%4];" \
        : "=r"((r)[0]), "=r"((r)[1]), "=r"((r)[2]), "=r"((r)[3]) : "r"(addr))
#define LDSM_X2(r, addr) \
    asm volatile("ldmatrix.sync.aligned.m8n8.x2.shared.b16 {%0,%1}, [%2];" \
        : "=r"((r)[0]), "=r"((r)[1]) : "r"(addr))
#define MMA_BF16(c, a, b) \
    asm volatile("mma.sync.aligned.m16n8k16.row.col.f32.bf16.bf16.f32 " \
        "{%0,%1,%2,%3}, {%4,%5,%6,%7}, {%8,%9}, {%0,%1,%2,%3};" \
        : "+f"((c)[0]), "+f"((c)[1]), "+f"((c)[2]), "+f"((c)[3]) \
        : "r"((a)[0]), "r"((a)[1]), "r"((a)[2]), "r"((a)[3]), "r"((b)[0]), "r"((b)[1]))

// ---------------------------------------------------------------------------
// sigma = ||W (W^T u / ||W^T u||)||  ->  store 1/sigma
// ---------------------------------------------------------------------------
__global__ void k_sigma(const float* __restrict__ W, const float* __restrict__ u) {
    __shared__ float v[F_OUT];
    __shared__ float red[128];
    __shared__ float n1_s;
    int t = threadIdx.x;

    if (t < F_OUT) {
        float s = 0.f;
        for (int i = 0; i < F_IN; i++) s += W[i * F_OUT + t] * u[i];
        v[t] = s;
    }
    __syncthreads();

    red[t] = (t < F_OUT) ? v[t] * v[t] : 0.f;
    __syncthreads();
    for (int s = 64; s > 0; s >>= 1) {
        if (t < s) red[t] += red[t + s];
        __syncthreads();
    }
    if (t == 0) n1_s = sqrtf(red[0]);
    __syncthreads();

    float g = 0.f;
    for (int j = 0; j < F_OUT; j++) g += W[t * F_OUT + j] * v[j];
    red[t] = g * g;
    __syncthreads();
    for (int s = 64; s > 0; s >>= 1) {
        if (t < s) red[t] += red[t + s];
        __syncthreads();
    }
    if (t == 0) {
        float n2 = sqrtf(red[0]);
        s_inv_sigma = n1_s / n2;
    }
}

// ---------------------------------------------------------------------------
__global__ void k_deg_acc(const int* __restrict__ ei,
                          const float* __restrict__ ew) {
    int e = blockIdx.x * blockDim.x + threadIdx.x;
    if (e < N_EDGES) {
        int col = ei[N_EDGES + e];
        float w = 1.f / (1.f + __expf(-ew[e]));
        atomicAdd(&s_deg[col], w);
    }
}

// dis = rsqrt(deg+1), reset deg (runs AFTER k_gemm which reads s_deg)
__global__ void k_dis() {
    int i = blockIdx.x * blockDim.x + threadIdx.x;
    if (i < N_NODES) {
        float d = s_deg[i] + 1.0f;
        s_dis[i] = rsqrtf(d);
        s_deg[i] = 0.0f;
    }
}

// ---------------------------------------------------------------------------
// Tensor GEMM via portable mma.sync (HMMA), bf16 3-term split:
//   xp = Ahi*Bhi + Ahi*Blo + Alo*Bhi      (error ~2^-18)
// Block: 128 rows x 64 cols, 128 threads (4 warps, 32 rows each).
// Epilogue: out = xp/(deg+1) + bias; stash xp for the edge kernel.
// ---------------------------------------------------------------------------
__global__ __launch_bounds__(128) void k_gemm(const float* __restrict__ x,
                                              const float* __restrict__ W,
                                              const float* __restrict__ bias,
                                              float* __restrict__ out) {
    extern __shared__ char smem[];
    uint32_t sb = smem_u32(smem);
    int tid = threadIdx.x;
    int wid = tid >> 5;
    int lane = tid & 31;
    int r0 = blockIdx.x * TM;

    float inv_sigma = s_inv_sigma;

    // ---- A: x[r0:r0+128, :] -> bf16 hi/lo into padded smem [128][AP]
    __nv_bfloat16* Ahi = (__nv_bfloat16*)(smem + SM_AHI);
    __nv_bfloat16* Alo = (__nv_bfloat16*)(smem + SM_ALO);
    #pragma unroll 4
    for (int it = 0; it < 32; it++) {
        int idx = it * 128 + tid;        // float4 slot, 4096 total
        int row = idx >> 5;
        int k4 = (idx & 31) * 4;
        int grow = r0 + row;
        float4 v = make_float4(0.f, 0.f, 0.f, 0.f);
        if (grow < N_NODES) v = *(const float4*)&x[(size_t)grow * F_IN + k4];

        float fv[4] = {v.x, v.y, v.z, v.w};
        __nv_bfloat16 h[4], l[4];
        #pragma unroll
        for (int j = 0; j < 4; j++) {
            h[j] = __float2bfloat16_rn(fv[j]);
            l[j] = __float2bfloat16_rn(fv[j] - __bfloat162float(h[j]));
        }
        int base = row * AP + k4;
        *(__nv_bfloat162*)&Ahi[base]     = __nv_bfloat162(h[0], h[1]);
        *(__nv_bfloat162*)&Ahi[base + 2] = __nv_bfloat162(h[2], h[3]);
        *(__nv_bfloat162*)&Alo[base]     = __nv_bfloat162(l[0], l[1]);
        *(__nv_bfloat162*)&Alo[base + 2] = __nv_bfloat162(l[2], l[3]);
    }

    // ---- B: B[n][k] = bf16(W[k][n] * inv_sigma), thread tid owns k=tid
    __nv_bfloat16* Bhi = (__nv_bfloat16*)(smem + SM_BHI);
    __nv_bfloat16* Blo = (__nv_bfloat16*)(smem + SM_BLO);
    {
        int k = tid;
        const float4* wr = (const float4*)(W + (size_t)k * F_OUT);
        #pragma unroll
        for (int n4 = 0; n4 < 16; n4++) {
            float4 wv = wr[n4];
            float vv[4] = {wv.x * inv_sigma, wv.y * inv_sigma,
                           wv.z * inv_sigma, wv.w * inv_sigma};
            #pragma unroll
            for (int j = 0; j < 4; j++) {
                int n = n4 * 4 + j;
                __nv_bfloat16 h = __float2bfloat16_rn(vv[j]);
                __nv_bfloat16 l = __float2bfloat16_rn(vv[j] - __bfloat162float(h));
                Bhi[n * AP + k] = h;
                Blo[n * AP + k] = l;
            }
        }
    }
    __syncthreads();

    // ---- fragment mainloop
    float acc[2][8][4];
    #pragma unroll
    for (int mt = 0; mt < 2; mt++)
        #pragma unroll
        for (int nt = 0; nt < 8; nt++)
            #pragma unroll
            for (int j = 0; j < 4; j++) acc[mt][nt][j] = 0.f;

    int lm = lane & 15;                // A row within m16 tile
    int lk = (lane >> 4) * 8;          // A k-offset (k8 half)
    int bn = lane & 7;                 // B n-row within n8 tile
    int bk = ((lane >> 3) & 1) * 8;    // B k-offset

    uint32_t aH0 = sb + SM_AHI + (uint32_t)(wid * 32 + lm) * AP * 2;
    uint32_t aH1 = aH0 + 16u * AP * 2;
    uint32_t aL0 = sb + SM_ALO + (uint32_t)(wid * 32 + lm) * AP * 2;
    uint32_t aL1 = aL0 + 16u * AP * 2;
    uint32_t bH  = sb + SM_BHI + (uint32_t)bn * AP * 2;
    uint32_t bL  = sb + SM_BLO + (uint32_t)bn * AP * 2;

    #pragma unroll
    for (int ks = 0; ks < 8; ks++) {
        int kb = ks * 16;
        uint32_t aoff = (uint32_t)(kb + lk) * 2;
        uint32_t boff = (uint32_t)(kb + bk) * 2;

        uint32_t ah0[4], ah1[4], al0[4], al1[4];
        LDSM_X4(ah0, aH0 + aoff);
        LDSM_X4(ah1, aH1 + aoff);
        LDSM_X4(al0, aL0 + aoff);
        LDSM_X4(al1, aL1 + aoff);

        #pragma unroll
        for (int nt = 0; nt < 8; nt++) {
            uint32_t bh[2], bl[2];
            uint32_t nstep = (uint32_t)(nt * 8) * AP * 2;
            LDSM_X2(bh, bH + nstep + boff);
            LDSM_X2(bl, bL + nstep + boff);
            MMA_BF16(acc[0][nt], ah0, bh);
            MMA_BF16(acc[0][nt], ah0, bl);
            MMA_BF16(acc[0][nt], al0, bh);
            MMA_BF16(acc[1][nt], ah1, bh);
            MMA_BF16(acc[1][nt], ah1, bl);
            MMA_BF16(acc[1][nt], al1, bh);
        }
    }

    // ---- epilogue: c0,c1 -> row lane>>2, cols n0,n0+1 ; c2,c3 -> row+8
    #pragma unroll
    for (int mt = 0; mt < 2; mt++) {
        int r1 = r0 + wid * 32 + mt * 16 + (lane >> 2);
        int r2 = r1 + 8;
        float id1 = 0.f, id2 = 0.f;
        if (r1 < N_NODES) id1 = 1.0f / (s_deg[r1] + 1.0f);
        if (r2 < N_NODES) id2 = 1.0f / (s_deg[r2] + 1.0f);
        #pragma unroll
        for (int nt = 0; nt < 8; nt++) {
            int n0 = nt * 8 + (lane & 3) * 2;
            float2 bv = *(const float2*)&bias[n0];
            if (r1 < N_NODES) {
                float2 xp = make_float2(acc[mt][nt][0], acc[mt][nt][1]);
                *(float2*)&s_xp[(size_t)r1 * F_OUT + n0] = xp;
                *(float2*)&out[(size_t)r1 * F_OUT + n0] =
                    make_float2(xp.x * id1 + bv.x, xp.y * id1 + bv.y);
            }
            if (r2 < N_NODES) {
                float2 xp = make_float2(acc[mt][nt][2], acc[mt][nt][3]);
                *(float2*)&s_xp[(size_t)r2 * F_OUT + n0] = xp;
                *(float2*)&out[(size_t)r2 * F_OUT + n0] =
                    make_float2(xp.x * id2 + bv.x, xp.y * id2 + bv.y);
            }
        }
    }
}

// ---------------------------------------------------------------------------
// Edge aggregation: out[col] += dis[row]*sigmoid(ew)*dis[col] * xp[row]
// 4 edges per warp, MLP=2 gathers, float4 RED scatter.
// ---------------------------------------------------------------------------
__global__ __launch_bounds__(256) void k_edge(const int* __restrict__ ei,
                                              const float* __restrict__ ew,
                                              float* __restrict__ out) {
    int gtid = blockIdx.x * blockDim.x + threadIdx.x;
    int lane = threadIdx.x & 31;
    int half = lane >> 4;
    int sub  = lane & 15;
    int ebase = (gtid >> 5) * 4 + half * 2;

    int   rowv[2], colv[2];
    float cf[2];
    #pragma unroll
    for (int j = 0; j < 2; j++) {
        int e = ebase + j;
        rowv[j] = ei[e];
        colv[j] = ei[N_EDGES + e];
        float w = 1.f / (1.f + __expf(-ew[e]));
        cf[j] = s_dis[rowv[j]] * w * s_dis[colv[j]];
    }

    float4 xv0 = *(const float4*)&s_xp[(size_t)rowv[0] * F_OUT + sub * 4];
    float4 xv1 = *(const float4*)&s_xp[(size_t)rowv[1] * F_OUT + sub * 4];

    float4 m0 = make_float4(xv0.x * cf[0], xv0.y * cf[0], xv0.z * cf[0], xv0.w * cf[0]);
    atomicAdd((float4*)&out[(size_t)colv[0] * F_OUT + sub * 4], m0);
    float4 m1 = make_float4(xv1.x * cf[1], xv1.y * cf[1], xv1.z * cf[1], xv1.w * cf[1]);
    atomicAdd((float4*)&out[(size_t)colv[1] * F_OUT + sub * 4], m1);
}

// ---------------------------------------------------------------------------
extern "C" void kernel_launch(void* const* d_in, const int* in_sizes, int n_in,
                              void* d_out, int out_size) {
    const float* x    = (const float*)d_in[0];
    const int*   ei   = (const int*)d_in[1];
    const float* W    = (const float*)d_in[2];
    const float* bias = (const float*)d_in[3];
    const float* ew   = (const float*)d_in[4];
    const float* u    = (const float*)d_in[5];
    float* out = (float*)d_out;

    cudaFuncSetAttribute(k_gemm, cudaFuncAttributeMaxDynamicSharedMemorySize, SM_TOTAL);

    k_sigma<<<1, 128>>>(W, u);
    k_deg_acc<<<(N_EDGES + 255) / 256, 256>>>(ei, ew);
    k_gemm<<<(N_NODES + TM - 1) / TM, 128, SM_TOTAL>>>(x, W, bias, out);
    k_dis<<<(N_NODES + 255) / 256, 256>>>();
    k_edge<<<18750, 256>>>(ei, ew, out);
}